// round 9
// baseline (speedup 1.0000x reference)
#include <cuda_runtime.h>
#include <math.h>

#define SEQ     16384
#define IN_DIM  512
#define HID     1024
#define OUT_DIM 256

#define NB      128     // scan blocks (<148 SMs => all co-resident)
#define SCAN_T  256     // 8 warps, one hidden row per warp

// ---- scratch (static __device__; no allocs anywhere) ----
__device__ float    g_xh[SEQ * HID];      // 64 MB  xh = input@Wxh.T + bias
__device__ float    g_outs[SEQ * HID];    // 64 MB  h_1..h_SEQ for GEMM3
__device__ unsigned g_hx[2][HID];         // tagged h exchange (tag in low 2 bits)
__device__ float    g_bias[HID];          // Wxh_b + Whh_b + bh

// morally-strong relaxed atomics (R4-proven mechanism)
__device__ __forceinline__ void st_relaxed_u32(unsigned* p, unsigned v) {
    asm volatile("st.relaxed.gpu.global.u32 [%0], %1;" :: "l"(p), "r"(v) : "memory");
}
__device__ __forceinline__ uint4 ld_relaxed_v4(const unsigned* p) {
    uint4 v;
    asm volatile("ld.relaxed.gpu.global.v4.u32 {%0,%1,%2,%3}, [%4];"
                 : "=r"(v.x), "=r"(v.y), "=r"(v.z), "=r"(v.w)
                 : "l"(p) : "memory");
    return v;
}

// ---------------------------------------------------------------- reset ----
__global__ void reset_kernel(const float* __restrict__ hidden,
                             const float* __restrict__ wxb,
                             const float* __restrict__ whb,
                             const float* __restrict__ bh) {
    int i = threadIdx.x;  // 1024 threads
    g_bias[i] = wxb[i] + whb[i] + bh[i];
    // slot 0 = h_0 with tag 0 (consumed at iter 0)
    g_hx[0][i] = (__float_as_uint(hidden[i]) & ~3u) | 0u;
    // slot 1 prefill: tag 2 (never matches iter-1's expected tag 1)
    g_hx[1][i] = 2u;
}

// --------------------------------------------------- generic NT fp32 GEMM --
// C[m][n] = sum_k A[m][k] * B[n][k] + bias[n]
__global__ void gemm_nt_bias(const float* __restrict__ A,
                             const float* __restrict__ B,
                             const float* __restrict__ bias,
                             float* __restrict__ C,
                             int M, int N, int K) {
    __shared__ float As[16][65];
    __shared__ float Bs[16][65];
    const int tid = threadIdx.x;
    const int bx = blockIdx.x;
    const int by = blockIdx.y;
    const int tm = (tid >> 4) << 2;
    const int tn = (tid & 15) << 2;
    const int lr = tid >> 2;
    const int lk = (tid & 3) << 2;

    const float* Ap = A + (size_t)(by * 64 + lr) * K + lk;
    const float* Bp = B + (size_t)(bx * 64 + lr) * K + lk;

    float acc[4][4] = {};

    for (int k0 = 0; k0 < K; k0 += 16) {
        float4 av = *(const float4*)(Ap + k0);
        float4 bv = *(const float4*)(Bp + k0);
        As[lk + 0][lr] = av.x; As[lk + 1][lr] = av.y;
        As[lk + 2][lr] = av.z; As[lk + 3][lr] = av.w;
        Bs[lk + 0][lr] = bv.x; Bs[lk + 1][lr] = bv.y;
        Bs[lk + 2][lr] = bv.z; Bs[lk + 3][lr] = bv.w;
        __syncthreads();
#pragma unroll
        for (int k = 0; k < 16; k++) {
            float ra[4], rb[4];
#pragma unroll
            for (int i = 0; i < 4; i++) ra[i] = As[k][tm + i];
#pragma unroll
            for (int j = 0; j < 4; j++) rb[j] = Bs[k][tn + j];
#pragma unroll
            for (int i = 0; i < 4; i++)
#pragma unroll
                for (int j = 0; j < 4; j++)
                    acc[i][j] += ra[i] * rb[j];
        }
        __syncthreads();
    }

    float bb[4];
#pragma unroll
    for (int j = 0; j < 4; j++) bb[j] = bias[bx * 64 + tn + j];
#pragma unroll
    for (int i = 0; i < 4; i++) {
        int row = by * 64 + tm + i;
        float* cp = C + (size_t)row * N + bx * 64 + tn;
#pragma unroll
        for (int j = 0; j < 4; j++) cp[j] = acc[i][j] + bb[j];
    }
}

// ------------------------- tag-validated dataflow scan (no barriers at all)
// Warp w of block b owns row b*8+w. Each iteration the warp gathers the full
// h_t directly from the tagged L2 exchange (8 relaxed v4 loads per lane,
// retried per-word on tag mismatch), computes its dot product in registers,
// and lane 0 publishes h_{t+1} with the next tag. Warps are fully
// independent: no __syncthreads, no fences, no atomics-on-counters.
__global__ void __launch_bounds__(SCAN_T, 1)
scan_kernel(const float* __restrict__ Whh) {
    const int bid  = blockIdx.x;
    const int tid  = threadIdx.x;
    const int wid  = tid >> 5;
    const int lane = tid & 31;
    const int row  = bid * 8 + wid;

    // Whh row slice in registers: w4[k] = Whh[row][k*128 + lane*4 .. +3]
    float4 w4[8];
#pragma unroll
    for (int k = 0; k < 8; k++)
        w4[k] = *(const float4*)&Whh[(size_t)row * HID + k * 128 + lane * 4];

    // xh pipeline (lane 0 only), depth 2
    float xh_c = 0.f, xh_n = 0.f;
    if (lane == 0) {
        xh_c = g_xh[row];
        xh_n = g_xh[(size_t)HID + row];
    }

#pragma unroll 1
    for (int t = 0; t < SEQ; t++) {
        const unsigned* slot = g_hx[t & 1];
        const unsigned  tg   = (unsigned)(t & 3);

        // gather h_t (tag-validated) and accumulate in one pass
        float a0 = 0.f, a1 = 0.f, a2 = 0.f, a3 = 0.f;
#pragma unroll
        for (int k = 0; k < 8; k++) {
            const unsigned* p = slot + k * 128 + lane * 4;
            uint4 u = ld_relaxed_v4(p);
            while (((u.x & 3u) != tg) | ((u.y & 3u) != tg) |
                   ((u.z & 3u) != tg) | ((u.w & 3u) != tg))
                u = ld_relaxed_v4(p);
            a0 = fmaf(w4[k].x, __uint_as_float(u.x), a0);
            a1 = fmaf(w4[k].y, __uint_as_float(u.y), a1);
            a2 = fmaf(w4[k].z, __uint_as_float(u.z), a2);
            a3 = fmaf(w4[k].w, __uint_as_float(u.w), a3);
        }
        float acc = (a0 + a1) + (a2 + a3);
#pragma unroll
        for (int o = 16; o > 0; o >>= 1)
            acc += __shfl_xor_sync(0xFFFFFFFFu, acc, o);

        if (lane == 0) {
            float hn = tanhf(xh_c + acc);
            unsigned nb = (__float_as_uint(hn) & ~3u) |
                          (unsigned)((t + 1) & 3);
            st_relaxed_u32(&g_hx[(t + 1) & 1][row], nb);      // publish
            g_outs[(size_t)t * HID + row] = __uint_as_float(nb);
            xh_c = xh_n;
            xh_n = (t + 2 < SEQ) ? __ldg(&g_xh[(size_t)(t + 2) * HID + row])
                                 : 0.f;
        }
    }
}

// ----------------------------------------------------------- row softmax ---
__global__ void softmax256(float* __restrict__ X) {
    const int r = blockIdx.x;
    const int tid = threadIdx.x;          // 256
    const int wid = tid >> 5, lane = tid & 31;
    __shared__ float red[8];

    float v = X[(size_t)r * OUT_DIM + tid];

    float m = v;
#pragma unroll
    for (int o = 16; o > 0; o >>= 1)
        m = fmaxf(m, __shfl_xor_sync(0xFFFFFFFFu, m, o));
    if (lane == 0) red[wid] = m;
    __syncthreads();
    if (tid == 0) {
        float mm = red[0];
#pragma unroll
        for (int i = 1; i < 8; i++) mm = fmaxf(mm, red[i]);
        red[0] = mm;
    }
    __syncthreads();
    const float bm = red[0];
    __syncthreads();

    float e = expf(v - bm);
    float s = e;
#pragma unroll
    for (int o = 16; o > 0; o >>= 1)
        s += __shfl_xor_sync(0xFFFFFFFFu, s, o);
    if (lane == 0) red[wid] = s;
    __syncthreads();
    if (tid == 0) {
        float ss = red[0];
#pragma unroll
        for (int i = 1; i < 8; i++) ss += red[i];
        red[0] = ss;
    }
    __syncthreads();
    X[(size_t)r * OUT_DIM + tid] = e / red[0];
}

// ------------------------------------------------------------------ launch -
extern "C" void kernel_launch(void* const* d_in, const int* in_sizes, int n_in,
                              void* d_out, int out_size) {
    const float* input  = (const float*)d_in[0];   // (SEQ, IN)
    const float* hidden = (const float*)d_in[1];   // (HID,)
    const float* Wxh_w  = (const float*)d_in[2];   // (HID, IN)
    const float* Wxh_b  = (const float*)d_in[3];   // (HID,)
    const float* Whh_w  = (const float*)d_in[4];   // (HID, HID)
    const float* Whh_b  = (const float*)d_in[5];   // (HID,)
    const float* bh     = (const float*)d_in[6];   // (HID,)
    const float* fc_w   = (const float*)d_in[7];   // (OUT, HID)
    const float* fc_b   = (const float*)d_in[8];   // (OUT,)
    float* out = (float*)d_out;                    // (SEQ, OUT)

    float* xh_ptr   = nullptr;
    float* outs_ptr = nullptr;
    float* bias_ptr = nullptr;
    cudaGetSymbolAddress((void**)&xh_ptr,   g_xh);
    cudaGetSymbolAddress((void**)&outs_ptr, g_outs);
    cudaGetSymbolAddress((void**)&bias_ptr, g_bias);

    // 0) fold biases + seed tagged exchange slots (every launch => replay-safe)
    reset_kernel<<<1, HID>>>(hidden, Wxh_b, Whh_b, bh);

    // 1) xh = input @ Wxh.T + bias        (M=SEQ, N=HID, K=IN)
    {
        dim3 grid(HID / 64, SEQ / 64);
        gemm_nt_bias<<<grid, 256>>>(input, Wxh_w, bias_ptr, xh_ptr,
                                    SEQ, HID, IN_DIM);
    }

    // 2) sequential recurrence (tag-validated dataflow, barrier-free)
    scan_kernel<<<NB, SCAN_T>>>(Whh_w);

    // 3) logits = outs @ fc_w.T + fc_b    (M=SEQ, N=OUT, K=HID) -> d_out
    {
        dim3 grid(OUT_DIM / 64, SEQ / 64);
        gemm_nt_bias<<<grid, 256>>>(outs_ptr, fc_w, fc_b, out,
                                    SEQ, OUT_DIM, HID);
    }

    // 4) softmax rows in place on d_out
    softmax256<<<SEQ, OUT_DIM>>>(out);
}

// round 10
// speedup vs baseline: 6.4676x; 6.4676x over previous
#include <cuda_runtime.h>
#include <math.h>

#define SEQ     16384
#define IN_DIM  512
#define HID     1024
#define OUT_DIM 256

#define NB      128     // scan blocks (<148 SMs => all co-resident)
#define SCAN_T  256     // 8 warps, one hidden row per warp

// ---- scratch (static __device__; no allocs anywhere) ----
__device__ float    g_xh[SEQ * HID];      // 64 MB  xh = input@Wxh.T + bias
__device__ float    g_outs[SEQ * HID];    // 64 MB  h_1..h_SEQ for GEMM3
__device__ unsigned g_hx[2][HID];         // tagged h exchange (tag = low 2 bits)
__device__ float    g_bias[HID];          // Wxh_b + Whh_b + bh

// morally-strong relaxed ops (R4/R9-proven mechanism)
__device__ __forceinline__ void st_relaxed_u32(unsigned* p, unsigned v) {
    asm volatile("st.relaxed.gpu.global.u32 [%0], %1;" :: "l"(p), "r"(v) : "memory");
}
__device__ __forceinline__ uint4 ld_relaxed_v4(const unsigned* p) {
    uint4 v;
    asm volatile("ld.relaxed.gpu.global.v4.u32 {%0,%1,%2,%3}, [%4];"
                 : "=r"(v.x), "=r"(v.y), "=r"(v.z), "=r"(v.w)
                 : "l"(p) : "memory");
    return v;
}

// ---------------------------------------------------------------- reset ----
__global__ void reset_kernel(const float* __restrict__ hidden,
                             const float* __restrict__ wxb,
                             const float* __restrict__ whb,
                             const float* __restrict__ bh) {
    int i = threadIdx.x;  // 1024 threads
    g_bias[i] = wxb[i] + whb[i] + bh[i];
    // slot 0 = h_0 with tag 0 (consumed at iter 0)
    g_hx[0][i] = (__float_as_uint(hidden[i]) & ~3u) | 0u;
    // slot 1 prefill: tag 2 (never matches iter-1's expected tag 1)
    g_hx[1][i] = 2u;
}

// --------------------------------------------------- generic NT fp32 GEMM --
// C[m][n] = sum_k A[m][k] * B[n][k] + bias[n]
__global__ void gemm_nt_bias(const float* __restrict__ A,
                             const float* __restrict__ B,
                             const float* __restrict__ bias,
                             float* __restrict__ C,
                             int M, int N, int K) {
    __shared__ float As[16][65];
    __shared__ float Bs[16][65];
    const int tid = threadIdx.x;
    const int bx = blockIdx.x;
    const int by = blockIdx.y;
    const int tm = (tid >> 4) << 2;
    const int tn = (tid & 15) << 2;
    const int lr = tid >> 2;
    const int lk = (tid & 3) << 2;

    const float* Ap = A + (size_t)(by * 64 + lr) * K + lk;
    const float* Bp = B + (size_t)(bx * 64 + lr) * K + lk;

    float acc[4][4] = {};

    for (int k0 = 0; k0 < K; k0 += 16) {
        float4 av = *(const float4*)(Ap + k0);
        float4 bv = *(const float4*)(Bp + k0);
        As[lk + 0][lr] = av.x; As[lk + 1][lr] = av.y;
        As[lk + 2][lr] = av.z; As[lk + 3][lr] = av.w;
        Bs[lk + 0][lr] = bv.x; Bs[lk + 1][lr] = bv.y;
        Bs[lk + 2][lr] = bv.z; Bs[lk + 3][lr] = bv.w;
        __syncthreads();
#pragma unroll
        for (int k = 0; k < 16; k++) {
            float ra[4], rb[4];
#pragma unroll
            for (int i = 0; i < 4; i++) ra[i] = As[k][tm + i];
#pragma unroll
            for (int j = 0; j < 4; j++) rb[j] = Bs[k][tn + j];
#pragma unroll
            for (int i = 0; i < 4; i++)
#pragma unroll
                for (int j = 0; j < 4; j++)
                    acc[i][j] += ra[i] * rb[j];
        }
        __syncthreads();
    }

    float bb[4];
#pragma unroll
    for (int j = 0; j < 4; j++) bb[j] = bias[bx * 64 + tn + j];
#pragma unroll
    for (int i = 0; i < 4; i++) {
        int row = by * 64 + tm + i;
        float* cp = C + (size_t)row * N + bx * 64 + tn;
#pragma unroll
        for (int j = 0; j < 4; j++) cp[j] = acc[i][j] + bb[j];
    }
}

// ---------------- tagged-staging persistent scan (one L2 trip per step) ----
// R2's block/MV structure, but the h staging load IS the synchronization:
// each thread polls its own 16B of the tagged exchange until all 4 words
// carry tag (t&3), stores them to smem, and the block proceeds. Producers
// publish h_{t+1} with tag ((t+1)&3) via one relaxed store. No flags, no
// fences, no atomics, no extra barriers.
__global__ void __launch_bounds__(SCAN_T, 1)
scan_kernel(const float* __restrict__ Whh) {
    const int bid  = blockIdx.x;
    const int tid  = threadIdx.x;
    const int wid  = tid >> 5;
    const int lane = tid & 31;
    const int row  = bid * 8 + wid;          // my warp's hidden row

    // Whh row slice in registers: w4[k] = Whh[row][k*128 + lane*4 .. +3]
    float4 w4[8];
#pragma unroll
    for (int k = 0; k < 8; k++)
        w4[k] = *(const float4*)&Whh[(size_t)row * HID + k * 128 + lane * 4];

    __shared__ float hs[HID];

    // xh pipeline (lane 0 of each warp), depth 2
    float xh_c = 0.f, xh_n = 0.f;
    if (lane == 0) {
        xh_c = g_xh[row];
        xh_n = g_xh[(size_t)HID + row];
    }

#pragma unroll 1
    for (int t = 0; t < SEQ; t++) {
        // ---- fused poll+stage: my 16B of h_t, tag-validated ----
        {
            const unsigned* p = g_hx[t & 1] + tid * 4;
            const unsigned  tg = (unsigned)(t & 3);
            uint4 u = ld_relaxed_v4(p);
            while (((u.x & 3u) != tg) | ((u.y & 3u) != tg) |
                   ((u.z & 3u) != tg) | ((u.w & 3u) != tg))
                u = ld_relaxed_v4(p);
            *(uint4*)&((unsigned*)hs)[tid * 4] = u;
        }
        __syncthreads();

        // ---- MV: acc = Whh[row] . h_t  (8 x LDS.128) ----
        float a0 = 0.f, a1 = 0.f, a2 = 0.f, a3 = 0.f;
#pragma unroll
        for (int k = 0; k < 8; k++) {
            float4 hv = *(const float4*)&hs[k * 128 + lane * 4];
            a0 = fmaf(w4[k].x, hv.x, a0);
            a1 = fmaf(w4[k].y, hv.y, a1);
            a2 = fmaf(w4[k].z, hv.z, a2);
            a3 = fmaf(w4[k].w, hv.w, a3);
        }
        float acc = (a0 + a1) + (a2 + a3);
#pragma unroll
        for (int o = 16; o > 0; o >>= 1)
            acc += __shfl_xor_sync(0xFFFFFFFFu, acc, o);

        if (lane == 0) {
            float hn = tanhf(xh_c + acc);
            unsigned nb = (__float_as_uint(hn) & ~3u) |
                          (unsigned)((t + 1) & 3);
            st_relaxed_u32(&g_hx[(t + 1) & 1][row], nb);      // publish h_{t+1}
            g_outs[(size_t)t * HID + row] = __uint_as_float(nb);
            xh_c = xh_n;
            xh_n = (t + 2 < SEQ) ? __ldg(&g_xh[(size_t)(t + 2) * HID + row])
                                 : 0.f;
        }
        __syncthreads();     // hs[] fully consumed before next stage overwrites
    }
}

// ----------------------------------------------------------- row softmax ---
__global__ void softmax256(float* __restrict__ X) {
    const int r = blockIdx.x;
    const int tid = threadIdx.x;          // 256
    const int wid = tid >> 5, lane = tid & 31;
    __shared__ float red[8];

    float v = X[(size_t)r * OUT_DIM + tid];

    float m = v;
#pragma unroll
    for (int o = 16; o > 0; o >>= 1)
        m = fmaxf(m, __shfl_xor_sync(0xFFFFFFFFu, m, o));
    if (lane == 0) red[wid] = m;
    __syncthreads();
    if (tid == 0) {
        float mm = red[0];
#pragma unroll
        for (int i = 1; i < 8; i++) mm = fmaxf(mm, red[i]);
        red[0] = mm;
    }
    __syncthreads();
    const float bm = red[0];
    __syncthreads();

    float e = expf(v - bm);
    float s = e;
#pragma unroll
    for (int o = 16; o > 0; o >>= 1)
        s += __shfl_xor_sync(0xFFFFFFFFu, s, o);
    if (lane == 0) red[wid] = s;
    __syncthreads();
    if (tid == 0) {
        float ss = red[0];
#pragma unroll
        for (int i = 1; i < 8; i++) ss += red[i];
        red[0] = ss;
    }
    __syncthreads();
    X[(size_t)r * OUT_DIM + tid] = e / red[0];
}

// ------------------------------------------------------------------ launch -
extern "C" void kernel_launch(void* const* d_in, const int* in_sizes, int n_in,
                              void* d_out, int out_size) {
    const float* input  = (const float*)d_in[0];   // (SEQ, IN)
    const float* hidden = (const float*)d_in[1];   // (HID,)
    const float* Wxh_w  = (const float*)d_in[2];   // (HID, IN)
    const float* Wxh_b  = (const float*)d_in[3];   // (HID,)
    const float* Whh_w  = (const float*)d_in[4];   // (HID, HID)
    const float* Whh_b  = (const float*)d_in[5];   // (HID,)
    const float* bh     = (const float*)d_in[6];   // (HID,)
    const float* fc_w   = (const float*)d_in[7];   // (OUT, HID)
    const float* fc_b   = (const float*)d_in[8];   // (OUT,)
    float* out = (float*)d_out;                    // (SEQ, OUT)

    float* xh_ptr   = nullptr;
    float* outs_ptr = nullptr;
    float* bias_ptr = nullptr;
    cudaGetSymbolAddress((void**)&xh_ptr,   g_xh);
    cudaGetSymbolAddress((void**)&outs_ptr, g_outs);
    cudaGetSymbolAddress((void**)&bias_ptr, g_bias);

    // 0) fold biases + seed tagged exchange slots (every launch => replay-safe)
    reset_kernel<<<1, HID>>>(hidden, Wxh_b, Whh_b, bh);

    // 1) xh = input @ Wxh.T + bias        (M=SEQ, N=HID, K=IN)
    {
        dim3 grid(HID / 64, SEQ / 64);
        gemm_nt_bias<<<grid, 256>>>(input, Wxh_w, bias_ptr, xh_ptr,
                                    SEQ, HID, IN_DIM);
    }

    // 2) sequential recurrence (tagged-staging dataflow persistent kernel)
    scan_kernel<<<NB, SCAN_T>>>(Whh_w);

    // 3) logits = outs @ fc_w.T + fc_b    (M=SEQ, N=OUT, K=HID) -> d_out
    {
        dim3 grid(OUT_DIM / 64, SEQ / 64);
        gemm_nt_bias<<<grid, 256>>>(outs_ptr, fc_w, fc_b, out,
                                    SEQ, OUT_DIM, HID);
    }

    // 4) softmax rows in place on d_out
    softmax256<<<SEQ, OUT_DIM>>>(out);
}

// round 11
// speedup vs baseline: 8.0223x; 1.2404x over previous
#include <cuda_runtime.h>
#include <math.h>

#define SEQ     16384
#define IN_DIM  512
#define HID     1024
#define OUT_DIM 256

#define NB      128     // scan blocks (<148 SMs => all co-resident)
#define SCAN_T  256     // 8 warps, one hidden row per warp

// ---- scratch (static __device__; no allocs anywhere) ----
__device__ float    g_xh[SEQ * HID];      // 64 MB  xh = input@Wxh.T + bias
__device__ float    g_outs[SEQ * HID];    // 64 MB  h_1..h_SEQ for GEMM3
__device__ unsigned g_hx[2][HID];         // tagged h exchange (tag = low 2 bits)
__device__ float    g_bias[HID];          // Wxh_b + Whh_b + bh

// morally-strong relaxed ops (R4/R9/R10-proven mechanism)
__device__ __forceinline__ void st_relaxed_v4(unsigned* p, uint4 v) {
    asm volatile("st.relaxed.gpu.global.v4.u32 [%0], {%1,%2,%3,%4};"
                 :: "l"(p), "r"(v.x), "r"(v.y), "r"(v.z), "r"(v.w) : "memory");
}
__device__ __forceinline__ uint4 ld_relaxed_v4(const unsigned* p) {
    uint4 v;
    asm volatile("ld.relaxed.gpu.global.v4.u32 {%0,%1,%2,%3}, [%4];"
                 : "=r"(v.x), "=r"(v.y), "=r"(v.z), "=r"(v.w)
                 : "l"(p) : "memory");
    return v;
}

// branch-free tanh: 1 - 2/(1+e^{2x}); MUFU-only (~50cyc), abs err ~1e-7,
// saturates correctly at +-inf arguments.
__device__ __forceinline__ float fast_tanh(float x) {
    float t = __expf(2.0f * x);
    return 1.0f - __fdividef(2.0f, 1.0f + t);
}

// ---------------------------------------------------------------- reset ----
__global__ void reset_kernel(const float* __restrict__ hidden,
                             const float* __restrict__ wxb,
                             const float* __restrict__ whb,
                             const float* __restrict__ bh) {
    int i = threadIdx.x;  // 1024 threads
    g_bias[i] = wxb[i] + whb[i] + bh[i];
    // slot 0 = h_0 with tag 0 (consumed at iter 0)
    g_hx[0][i] = (__float_as_uint(hidden[i]) & ~3u) | 0u;
    // slot 1 prefill: tag 2 (never matches iter-1's expected tag 1)
    g_hx[1][i] = 2u;
}

// --------------------------------------------------- generic NT fp32 GEMM --
// C[m][n] = sum_k A[m][k] * B[n][k] + bias[n]
__global__ void gemm_nt_bias(const float* __restrict__ A,
                             const float* __restrict__ B,
                             const float* __restrict__ bias,
                             float* __restrict__ C,
                             int M, int N, int K) {
    __shared__ float As[16][65];
    __shared__ float Bs[16][65];
    const int tid = threadIdx.x;
    const int bx = blockIdx.x;
    const int by = blockIdx.y;
    const int tm = (tid >> 4) << 2;
    const int tn = (tid & 15) << 2;
    const int lr = tid >> 2;
    const int lk = (tid & 3) << 2;

    const float* Ap = A + (size_t)(by * 64 + lr) * K + lk;
    const float* Bp = B + (size_t)(bx * 64 + lr) * K + lk;

    float acc[4][4] = {};

    for (int k0 = 0; k0 < K; k0 += 16) {
        float4 av = *(const float4*)(Ap + k0);
        float4 bv = *(const float4*)(Bp + k0);
        As[lk + 0][lr] = av.x; As[lk + 1][lr] = av.y;
        As[lk + 2][lr] = av.z; As[lk + 3][lr] = av.w;
        Bs[lk + 0][lr] = bv.x; Bs[lk + 1][lr] = bv.y;
        Bs[lk + 2][lr] = bv.z; Bs[lk + 3][lr] = bv.w;
        __syncthreads();
#pragma unroll
        for (int k = 0; k < 16; k++) {
            float ra[4], rb[4];
#pragma unroll
            for (int i = 0; i < 4; i++) ra[i] = As[k][tm + i];
#pragma unroll
            for (int j = 0; j < 4; j++) rb[j] = Bs[k][tn + j];
#pragma unroll
            for (int i = 0; i < 4; i++)
#pragma unroll
                for (int j = 0; j < 4; j++)
                    acc[i][j] += ra[i] * rb[j];
        }
        __syncthreads();
    }

    float bb[4];
#pragma unroll
    for (int j = 0; j < 4; j++) bb[j] = bias[bx * 64 + tn + j];
#pragma unroll
    for (int i = 0; i < 4; i++) {
        int row = by * 64 + tm + i;
        float* cp = C + (size_t)row * N + bx * 64 + tn;
#pragma unroll
        for (int j = 0; j < 4; j++) cp[j] = acc[i][j] + bb[j];
    }
}

// -------- tagged-staging persistent scan with aggregated 16B publishes ----
// As R10 (fused poll+stage, tags in low 2 mantissa bits), but each block's
// 8 h-values are published as TWO st.relaxed.v4 by threads 0-1 after an
// intra-block gather, so every consumer's polled 16B arrives atomically
// from a single store: one-retry detection instead of multi-word skew.
__global__ void __launch_bounds__(SCAN_T, 1)
scan_kernel(const float* __restrict__ Whh) {
    const int bid  = blockIdx.x;
    const int tid  = threadIdx.x;
    const int wid  = tid >> 5;
    const int lane = tid & 31;
    const int row  = bid * 8 + wid;          // my warp's hidden row

    // Whh row slice in registers: w4[k] = Whh[row][k*128 + lane*4 .. +3]
    float4 w4[8];
#pragma unroll
    for (int k = 0; k < 8; k++)
        w4[k] = *(const float4*)&Whh[(size_t)row * HID + k * 128 + lane * 4];

    __shared__ float    hs[HID];
    __shared__ unsigned hout[8];             // tagged h_{t+1} of this block

    // xh pipeline (lane 0 of each warp), depth 2
    float xh_c = 0.f, xh_n = 0.f;
    if (lane == 0) {
        xh_c = g_xh[row];
        xh_n = g_xh[(size_t)HID + row];
    }

#pragma unroll 1
    for (int t = 0; t < SEQ; t++) {
        // ---- fused poll+stage: my 16B of h_t (single-producer, atomic) ----
        {
            const unsigned* p = g_hx[t & 1] + tid * 4;
            const unsigned  tg = (unsigned)(t & 3);
            uint4 u = ld_relaxed_v4(p);
            while (((u.x & 3u) != tg) | ((u.y & 3u) != tg) |
                   ((u.z & 3u) != tg) | ((u.w & 3u) != tg))
                u = ld_relaxed_v4(p);
            *(uint4*)&((unsigned*)hs)[tid * 4] = u;
        }
        __syncthreads();

        // ---- MV: acc = Whh[row] . h_t  (8 x LDS.128) ----
        float a0 = 0.f, a1 = 0.f, a2 = 0.f, a3 = 0.f;
#pragma unroll
        for (int k = 0; k < 8; k++) {
            float4 hv = *(const float4*)&hs[k * 128 + lane * 4];
            a0 = fmaf(w4[k].x, hv.x, a0);
            a1 = fmaf(w4[k].y, hv.y, a1);
            a2 = fmaf(w4[k].z, hv.z, a2);
            a3 = fmaf(w4[k].w, hv.w, a3);
        }
        float acc = (a0 + a1) + (a2 + a3);
#pragma unroll
        for (int o = 16; o > 0; o >>= 1)
            acc += __shfl_xor_sync(0xFFFFFFFFu, acc, o);

        if (lane == 0) {
            float hn = fast_tanh(xh_c + acc);
            unsigned nb = (__float_as_uint(hn) & ~3u) |
                          (unsigned)((t + 1) & 3);
            hout[wid] = nb;                               // stage for publish
            g_outs[(size_t)t * HID + row] = __uint_as_float(nb);
            xh_c = xh_n;
            xh_n = (t + 2 < SEQ) ? __ldg(&g_xh[(size_t)(t + 2) * HID + row])
                                 : 0.f;
        }
        __syncthreads();       // hout complete; hs fully consumed

        // ---- aggregated publish: two 16B stores cover the block's 8 rows --
        if (tid < 2)
            st_relaxed_v4(&g_hx[(t + 1) & 1][bid * 8 + tid * 4],
                          *(const uint4*)&hout[tid * 4]);
    }
}

// ----------------------------------------------------------- row softmax ---
__global__ void softmax256(float* __restrict__ X) {
    const int r = blockIdx.x;
    const int tid = threadIdx.x;          // 256
    const int wid = tid >> 5, lane = tid & 31;
    __shared__ float red[8];

    float v = X[(size_t)r * OUT_DIM + tid];

    float m = v;
#pragma unroll
    for (int o = 16; o > 0; o >>= 1)
        m = fmaxf(m, __shfl_xor_sync(0xFFFFFFFFu, m, o));
    if (lane == 0) red[wid] = m;
    __syncthreads();
    if (tid == 0) {
        float mm = red[0];
#pragma unroll
        for (int i = 1; i < 8; i++) mm = fmaxf(mm, red[i]);
        red[0] = mm;
    }
    __syncthreads();
    const float bm = red[0];
    __syncthreads();

    float e = expf(v - bm);
    float s = e;
#pragma unroll
    for (int o = 16; o > 0; o >>= 1)
        s += __shfl_xor_sync(0xFFFFFFFFu, s, o);
    if (lane == 0) red[wid] = s;
    __syncthreads();
    if (tid == 0) {
        float ss = red[0];
#pragma unroll
        for (int i = 1; i < 8; i++) ss += red[i];
        red[0] = ss;
    }
    __syncthreads();
    X[(size_t)r * OUT_DIM + tid] = e / red[0];
}

// ------------------------------------------------------------------ launch -
extern "C" void kernel_launch(void* const* d_in, const int* in_sizes, int n_in,
                              void* d_out, int out_size) {
    const float* input  = (const float*)d_in[0];   // (SEQ, IN)
    const float* hidden = (const float*)d_in[1];   // (HID,)
    const float* Wxh_w  = (const float*)d_in[2];   // (HID, IN)
    const float* Wxh_b  = (const float*)d_in[3];   // (HID,)
    const float* Whh_w  = (const float*)d_in[4];   // (HID, HID)
    const float* Whh_b  = (const float*)d_in[5];   // (HID,)
    const float* bh     = (const float*)d_in[6];   // (HID,)
    const float* fc_w   = (const float*)d_in[7];   // (OUT, HID)
    const float* fc_b   = (const float*)d_in[8];   // (OUT,)
    float* out = (float*)d_out;                    // (SEQ, OUT)

    float* xh_ptr   = nullptr;
    float* outs_ptr = nullptr;
    float* bias_ptr = nullptr;
    cudaGetSymbolAddress((void**)&xh_ptr,   g_xh);
    cudaGetSymbolAddress((void**)&outs_ptr, g_outs);
    cudaGetSymbolAddress((void**)&bias_ptr, g_bias);

    // 0) fold biases + seed tagged exchange slots (every launch => replay-safe)
    reset_kernel<<<1, HID>>>(hidden, Wxh_b, Whh_b, bh);

    // 1) xh = input @ Wxh.T + bias        (M=SEQ, N=HID, K=IN)
    {
        dim3 grid(HID / 64, SEQ / 64);
        gemm_nt_bias<<<grid, 256>>>(input, Wxh_w, bias_ptr, xh_ptr,
                                    SEQ, HID, IN_DIM);
    }

    // 2) sequential recurrence (tagged-staging, aggregated publishes)
    scan_kernel<<<NB, SCAN_T>>>(Whh_w);

    // 3) logits = outs @ fc_w.T + fc_b    (M=SEQ, N=OUT, K=HID) -> d_out
    {
        dim3 grid(OUT_DIM / 64, SEQ / 64);
        gemm_nt_bias<<<grid, 256>>>(outs_ptr, fc_w, fc_b, out,
                                    SEQ, OUT_DIM, HID);
    }

    // 4) softmax rows in place on d_out
    softmax256<<<SEQ, OUT_DIM>>>(out);
}